// round 11
// baseline (speedup 1.0000x reference)
#include <cuda_runtime.h>
#include <cuda_fp16.h>
#include <cstdint>

// Problem constants (fixed by reference)
#define B_   8192   // batch
#define D_   256    // input dim
#define C_   512    // num centers
#define NORD 9      // order+1
#define F_   256    // output dim
#define KTOT (C_ * NORD)   // 4608

// ---------------- scratch (static device globals; no allocation) ----------
__device__ __align__(16) float g_dist[(size_t)B_ * C_];   // 16 MB
__device__ float g_x2[B_];
__device__ float g_c2[C_];
__device__ float g_bias_part[16][F_];
__device__ unsigned int g_minmax[2];
// W packed in mma-fragment order, single fp16 (record = 16B uint4)
__device__ __align__(16) uint4 g_wf[2 * 32 * NORD * 8 * 32];   // 2.4 MB
// x packed in A-fragment order, single fp16: [mi(512)][kt(16)][lane(32)]
__device__ __align__(16) uint4 g_xf[(B_ / 16) * 16 * 32];      // 4 MB
// centers packed in B-fragment order, single fp16
__device__ __align__(16) uint4 g_cf[(C_ / 16) * 16 * 32];      // 256 KB

// ==================== small helpers ========================================
__device__ __forceinline__ void mma_fp16(float* d, const uint32_t* a,
                                         uint32_t b0, uint32_t b1) {
    asm volatile(
        "mma.sync.aligned.m16n8k16.row.col.f32.f16.f16.f32 "
        "{%0,%1,%2,%3}, {%4,%5,%6,%7}, {%8,%9}, {%0,%1,%2,%3};"
        : "+f"(d[0]), "+f"(d[1]), "+f"(d[2]), "+f"(d[3])
        : "r"(a[0]), "r"(a[1]), "r"(a[2]), "r"(a[3]), "r"(b0), "r"(b1));
}

__device__ __forceinline__ uint32_t pack_h(float v0, float v1) {
    __half2 h = __floats2half2_rn(v0, v1);
    return *(uint32_t*)&h;
}

// ---------------- fused prep kernel ----------------------------------------
// Block ranges (bias first — short blocks, no tail):
//   [0, 16)              : P0-bias partial sums (32 centers each) + minmax init
//   [16, 16+1024)        : pack x into A-fragment order (fp16)
//   [.., +64)            : pack centers into B-fragment order (fp16)
//   [.., +576)           : pack W into B-fragment order (fp16)
//   [.., +1088)          : row squared norms (x then centers)
#define NB_BIAS 16
#define NB_PX  (NB_BIAS + 1024)
#define NB_PC  (NB_PX + 64)
#define NB_PW  (NB_PC + 576)
#define NB_SQ  (NB_PW + 1088)
#define NB_ALL NB_SQ

__global__ void __launch_bounds__(256) k_prep_all(const float* __restrict__ x,
                                                  const float* __restrict__ cen,
                                                  const float* __restrict__ w) {
    const int b   = blockIdx.x;
    const int tid = threadIdx.x;

    if (b < NB_BIAS) {
        // ---- bias partial: centers [32b, 32b+32), coalesced across tid ----
        if (b == 0 && tid == 0) { g_minmax[0] = 0x7f800000u; g_minmax[1] = 0u; }
        float s = 0.f;
        const float* wp = w + (size_t)(b * 32) * (NORD * F_) + tid;
        #pragma unroll
        for (int c = 0; c < 32; c++)
            s += wp[(size_t)c * (NORD * F_)];
        g_bias_part[b][tid] = s;
    } else if (b < NB_PX) {
        // ---- pack x ----
        int gid  = (b - NB_BIAS) * 256 + tid;    // (mi*16+kt)*32+lane
        int lane = gid & 31;
        int kt   = (gid >> 5) & 15;
        int mi   = gid >> 9;
        int c0 = lane & 3, lr = lane >> 2;
        const float* px = x + (size_t)(mi * 16 + lr) * D_ + kt * 16 + 2 * c0;
        float2 v0 = *(const float2*)(px);
        float2 v1 = *(const float2*)(px + 8 * D_);
        float2 v2 = *(const float2*)(px + 8);
        float2 v3 = *(const float2*)(px + 8 * D_ + 8);
        g_xf[gid] = make_uint4(pack_h(v0.x, v0.y), pack_h(v1.x, v1.y),
                               pack_h(v2.x, v2.y), pack_h(v3.x, v3.y));
    } else if (b < NB_PC) {
        // ---- pack centers ----
        int gid  = (b - NB_PX) * 256 + tid;      // (ni*16+kt)*32+lane
        int lane = gid & 31;
        int kt   = (gid >> 5) & 15;
        int ni   = gid >> 9;
        int c0 = lane & 3, lr = lane >> 2;
        const float* pc = cen + (size_t)(ni * 16 + lr) * D_ + kt * 16 + 2 * c0;
        float2 v0 = *(const float2*)(pc);
        float2 v1 = *(const float2*)(pc + 8);
        float2 v2 = *(const float2*)(pc + 8 * D_);
        float2 v3 = *(const float2*)(pc + 8 * D_ + 8);
        g_cf[gid] = make_uint4(pack_h(v0.x, v0.y), pack_h(v1.x, v1.y),
                               pack_h(v2.x, v2.y), pack_h(v3.x, v3.y));
    } else if (b < NB_PW) {
        // ---- pack W ----
        const int idx  = b - NB_PC;
        const int cb   = idx & 31;
        const int fb   = (idx >> 5) & 1;
        const int kt   = idx >> 6;         // 0..8
        const int lane = tid & 31;
        const int n16  = tid >> 5;         // 0..7
        const int c0   = lane & 3;
        const int fr   = lane >> 2;
        const int f0   = fb * 128 + n16 * 16 + fr;
        const int ci0  = cb * 16 + 2 * c0;
        float v[2][4];
        #pragma unroll
        for (int e = 0; e < 2; e++) {
            v[e][0] = w[((size_t)(ci0 + 0) * NORD + kt) * F_ + f0 + e * 8];
            v[e][1] = w[((size_t)(ci0 + 1) * NORD + kt) * F_ + f0 + e * 8];
            v[e][2] = w[((size_t)(ci0 + 8) * NORD + kt) * F_ + f0 + e * 8];
            v[e][3] = w[((size_t)(ci0 + 9) * NORD + kt) * F_ + f0 + e * 8];
        }
        g_wf[(((size_t)(fb * 32 + cb) * NORD + kt) * 8 + n16) * 32 + lane] =
            make_uint4(pack_h(v[0][0], v[0][1]), pack_h(v[0][2], v[0][3]),
                       pack_h(v[1][0], v[1][1]), pack_h(v[1][2], v[1][3]));
    } else {
        // ---- row squared norms ----
        int warp = (b - NB_PW) * 8 + (tid >> 5);
        int lane = tid & 31;
        if (warp >= B_ + C_) return;
        const float* src;
        float* dst;
        if (warp < B_) { src = x   + (size_t)warp * D_;        dst = &g_x2[warp]; }
        else           { src = cen + (size_t)(warp - B_) * D_; dst = &g_c2[warp - B_]; }
        float s = 0.f;
        const float4* p = (const float4*)src;
        #pragma unroll
        for (int i = lane; i < D_ / 4; i += 32) {
            float4 v = p[i];
            s += v.x * v.x + v.y * v.y + v.z * v.z + v.w * v.w;
        }
        #pragma unroll
        for (int o = 16; o > 0; o >>= 1) s += __shfl_xor_sync(0xffffffffu, s, o);
        if (lane == 0) *dst = s;
    }
}

// ---------------- kernel 4: tensorized distance GEMM + min/max ------------
// 128 CTAs (one wave), each computes 2 m-tiles of 128 rows.
__global__ void __launch_bounds__(256) k_dist_mma() {
    __shared__ unsigned int s_min, s_max;
    const int tid  = threadIdx.x;
    const int wid  = tid >> 5;
    const int lane = tid & 31;
    const int wm   = wid & 3;
    const int wn   = wid >> 2;
    const int n0   = blockIdx.x * 128;
    const int tig  = lane & 3;
    const int lr   = lane >> 2;

    if (tid == 0) { s_min = 0x7f800000u; s_max = 0u; }

    float lmin = 3.4e38f, lmax = 0.f;

    for (int mb = 0; mb < 2; mb++) {
        const int m0 = (blockIdx.y * 2 + mb) * 128;

        float acc[2][8][4];
        #pragma unroll
        for (int mt = 0; mt < 2; mt++)
            #pragma unroll
            for (int j = 0; j < 8; j++)
                #pragma unroll
                for (int e = 0; e < 4; e++) acc[mt][j][e] = 0.0f;

        const int mi0 = (m0 >> 4) + wm * 2;
        const int ni0 = (n0 >> 4) + wn * 4;

        #pragma unroll 4
        for (int kt = 0; kt < 16; kt++) {
            uint4 a[2], b[4];
            #pragma unroll
            for (int mt = 0; mt < 2; mt++)
                a[mt] = g_xf[(size_t)((mi0 + mt) * 16 + kt) * 32 + lane];
            #pragma unroll
            for (int g = 0; g < 4; g++)
                b[g] = g_cf[(size_t)((ni0 + g) * 16 + kt) * 32 + lane];
            #pragma unroll
            for (int g = 0; g < 4; g++)
                #pragma unroll
                for (int mt = 0; mt < 2; mt++) {
                    mma_fp16(acc[mt][g * 2 + 0], (const uint32_t*)&a[mt], b[g].x, b[g].y);
                    mma_fp16(acc[mt][g * 2 + 1], (const uint32_t*)&a[mt], b[g].z, b[g].w);
                }
        }

        // epilogue: distances + min/max
        float x2r[2][2];
        #pragma unroll
        for (int mt = 0; mt < 2; mt++)
            #pragma unroll
            for (int rh = 0; rh < 2; rh++)
                x2r[mt][rh] = g_x2[m0 + wm * 32 + mt * 16 + rh * 8 + lr];

        #pragma unroll
        for (int mt = 0; mt < 2; mt++) {
            #pragma unroll
            for (int j = 0; j < 8; j++) {
                const int n = n0 + wn * 64 + j * 8 + tig * 2;
                float2 c2v = *(const float2*)&g_c2[n];
                #pragma unroll
                for (int rh = 0; rh < 2; rh++) {
                    float xx = x2r[mt][rh];
                    float d0 = sqrtf(fmaxf(xx + c2v.x - 2.0f * acc[mt][j][rh * 2 + 0], 0.f));
                    float d1 = sqrtf(fmaxf(xx + c2v.y - 2.0f * acc[mt][j][rh * 2 + 1], 0.f));
                    lmin = fminf(lmin, fminf(d0, d1));
                    lmax = fmaxf(lmax, fmaxf(d0, d1));
                    const int row = m0 + wm * 32 + mt * 16 + rh * 8 + lr;
                    *(float2*)&g_dist[(size_t)row * C_ + n] = make_float2(d0, d1);
                }
            }
        }
    }

    #pragma unroll
    for (int o = 16; o > 0; o >>= 1) {
        lmin = fminf(lmin, __shfl_xor_sync(0xffffffffu, lmin, o));
        lmax = fmaxf(lmax, __shfl_xor_sync(0xffffffffu, lmax, o));
    }
    __syncthreads();
    if (lane == 0) {
        atomicMin(&s_min, __float_as_uint(lmin));
        atomicMax(&s_max, __float_as_uint(lmax));
    }
    __syncthreads();
    if (tid == 0) {
        atomicMin(&g_minmax[0], s_min);
        atomicMax(&g_minmax[1], s_max);
    }
}

// ---------------- kernel 5: register-resident fp16 fragment GEMM -----------
// CTA tile 128x64 (grid 4x64 = 256 CTAs, 2 CTAs/SM -> 4 warps/SMSP).
// A = Legendre basis single fp16 (recurrence fp32), B = W single fp16.
// kt=0 (P0==1) folded into exact fp32 bias; GEMM runs orders 1..8 only.
#define IDX(mt, r, c) (((mt) * 2 + (r)) * 4 + (c))

__global__ void __launch_bounds__(256, 2) k_out_frag(float* __restrict__ out) {
    const int tid  = threadIdx.x;
    const int wid  = tid >> 5;
    const int lane = tid & 31;
    const int wm   = wid & 3;     // 4 m-subtiles of 32
    const int wn   = wid >> 2;    // 2 n-subtiles of 32
    const int m0   = blockIdx.y * 128;
    const int bx   = blockIdx.x;  // 0..3 (f-blocks of 64)
    const int f0   = bx * 64;
    const int c0   = lane & 3;
    const int lr   = lane >> 2;

    const float dmin  = __uint_as_float(g_minmax[0]);
    const float dmax  = __uint_as_float(g_minmax[1]);
    const float scale = 2.0f / (dmax - dmin);
    const float tc    = fmaf(-dmin, scale, -1.0f);

    const float* dp[4];
    #pragma unroll
    for (int q = 0; q < 4; q++) {
        int row = m0 + wm * 32 + (q >> 1) * 16 + (q & 1) * 8 + lr;
        dp[q] = g_dist + (size_t)row * C_ + 2 * c0;
    }

    // record = 16B; strides: g:512B, kt:4096B, cb:36864B
    // n16 index within fb2-half = (bx&1)*4 + wn*2 + g
    const char* wfb = (const char*)g_wf
        + (((size_t)((bx >> 1) * 32) * (NORD * 8)) + (bx & 1) * 4 + wn * 2) * 512
        + lane * 16;

    // init accumulators with the exact P0 bias (sum of 16 partials)
    float acc[2][4][4];
    #pragma unroll
    for (int j = 0; j < 4; j++) {
        const int fz = f0 + wn * 32 + j * 8 + (lane & 3) * 2;
        float2 bz = make_float2(0.f, 0.f);
        #pragma unroll
        for (int p = 0; p < 16; p++) {
            float2 v = *(const float2*)&g_bias_part[p][fz];
            bz.x += v.x;
            bz.y += v.y;
        }
        #pragma unroll
        for (int mt = 0; mt < 2; mt++) {
            acc[mt][j][0] = bz.x; acc[mt][j][1] = bz.y;
            acc[mt][j][2] = bz.x; acc[mt][j][3] = bz.y;
        }
    }

    for (int cb = 0; cb < 32; cb++) {
        float t[16], pa[16], pb[16];
        #pragma unroll
        for (int q = 0; q < 4; q++) {
            float2 a0 = *(const float2*)(dp[q] + cb * 16);
            float2 a1 = *(const float2*)(dp[q] + cb * 16 + 8);
            t[q * 4 + 0] = fmaf(a0.x, scale, tc);
            t[q * 4 + 1] = fmaf(a0.y, scale, tc);
            t[q * 4 + 2] = fmaf(a1.x, scale, tc);
            t[q * 4 + 3] = fmaf(a1.y, scale, tc);
        }
        #pragma unroll
        for (int i = 0; i < 16; i++) { pa[i] = 1.0f; pb[i] = t[i]; }

        const char* wpc = wfb + (size_t)cb * (NORD * 8 * 512);

        #pragma unroll
        for (int kt = 1; kt < NORD; kt++) {
            // ---- B fragments for the 2 n16-groups of this kt ----
            const char* wpt = wpc + (size_t)kt * 4096;
            uint4 b[2];
            #pragma unroll
            for (int g = 0; g < 2; g++)
                b[g] = *(const uint4*)(wpt + g * 512);

            // ---- A fragments for order kt (single fp16) ----
            uint32_t ah[2][4];
            if (kt >= 2) {
                const float an = (2.0f * kt - 1.0f) / (float)kt;
                const float bn = (float)(kt - 1) / (float)kt;
                #pragma unroll
                for (int i = 0; i < 16; i++) {
                    float p2 = an * t[i] * pb[i] - bn * pa[i];
                    pa[i] = pb[i];
                    pb[i] = p2;
                }
            }
            #pragma unroll
            for (int mt = 0; mt < 2; mt++) {
                ah[mt][0] = pack_h(pb[IDX(mt,0,0)], pb[IDX(mt,0,1)]);
                ah[mt][1] = pack_h(pb[IDX(mt,1,0)], pb[IDX(mt,1,1)]);
                ah[mt][2] = pack_h(pb[IDX(mt,0,2)], pb[IDX(mt,0,3)]);
                ah[mt][3] = pack_h(pb[IDX(mt,1,2)], pb[IDX(mt,1,3)]);
            }

            // 8 independent mmas
            #pragma unroll
            for (int g = 0; g < 2; g++)
                #pragma unroll
                for (int mt = 0; mt < 2; mt++) {
                    mma_fp16(acc[mt][g * 2 + 0], ah[mt], b[g].x, b[g].y);
                    mma_fp16(acc[mt][g * 2 + 1], ah[mt], b[g].z, b[g].w);
                }
        }
    }

    // epilogue
    {
        const int g   = lane >> 2;
        const int tig = lane & 3;
        #pragma unroll
        for (int mt = 0; mt < 2; mt++) {
            const int mb = m0 + wm * 32 + mt * 16;
            #pragma unroll
            for (int j = 0; j < 4; j++) {
                const int f = f0 + wn * 32 + j * 8 + tig * 2;
                float2 lo = make_float2(acc[mt][j][0], acc[mt][j][1]);
                float2 hi = make_float2(acc[mt][j][2], acc[mt][j][3]);
                *(float2*)(out + (size_t)(mb + g)     * F_ + f) = lo;
                *(float2*)(out + (size_t)(mb + g + 8) * F_ + f) = hi;
            }
        }
    }
}

// ---------------- launch ---------------------------------------------------
extern "C" void kernel_launch(void* const* d_in, const int* in_sizes, int n_in,
                              void* d_out, int out_size) {
    const float* x   = (const float*)d_in[0];   // [8192,256]
    const float* cen = (const float*)d_in[1];   // [512,256]
    const float* w   = (const float*)d_in[2];   // [512,9,256]
    float* out = (float*)d_out;                 // [8192,256]

    k_prep_all<<<NB_ALL, 256>>>(x, cen, w);
    k_dist_mma<<<dim3(C_ / 128, B_ / 256), 256>>>();
    k_out_frag<<<dim3(F_ / 64, B_ / 128), 256>>>(out);
}

// round 12
// speedup vs baseline: 1.1579x; 1.1579x over previous
#include <cuda_runtime.h>
#include <cuda_fp16.h>
#include <cstdint>

// Problem constants (fixed by reference)
#define B_   8192   // batch
#define D_   256    // input dim
#define C_   512    // num centers
#define NORD 9      // order+1
#define F_   256    // output dim
#define KTOT (C_ * NORD)   // 4608

// ---------------- scratch (static device globals; no allocation) ----------
__device__ __align__(16) float g_dist[(size_t)B_ * C_];   // 16 MB
__device__ float g_x2[B_];
__device__ float g_c2[C_];
__device__ float g_bias_part[16][F_];
__device__ unsigned int g_minmax[2];
// W packed in mma-fragment order, single fp16 (record = 16B uint4)
__device__ __align__(16) uint4 g_wf[2 * 32 * NORD * 8 * 32];   // 2.4 MB
// x packed in A-fragment order, single fp16: [mi(512)][kt(16)][lane(32)]
__device__ __align__(16) uint4 g_xf[(B_ / 16) * 16 * 32];      // 4 MB
// centers packed in B-fragment order, single fp16
__device__ __align__(16) uint4 g_cf[(C_ / 16) * 16 * 32];      // 256 KB

// ==================== small helpers ========================================
__device__ __forceinline__ void mma_fp16(float* d, const uint32_t* a,
                                         uint32_t b0, uint32_t b1) {
    asm volatile(
        "mma.sync.aligned.m16n8k16.row.col.f32.f16.f16.f32 "
        "{%0,%1,%2,%3}, {%4,%5,%6,%7}, {%8,%9}, {%0,%1,%2,%3};"
        : "+f"(d[0]), "+f"(d[1]), "+f"(d[2]), "+f"(d[3])
        : "r"(a[0]), "r"(a[1]), "r"(a[2]), "r"(a[3]), "r"(b0), "r"(b1));
}

__device__ __forceinline__ uint32_t pack_h(float v0, float v1) {
    __half2 h = __floats2half2_rn(v0, v1);
    return *(uint32_t*)&h;
}

// ---------------- fused prep kernel ----------------------------------------
// Block ranges (bias first — short blocks, no tail):
//   [0, 16)              : P0-bias partial sums (32 centers each) + minmax init
//   [16, 16+1024)        : pack x into A-fragment order (fp16)
//   [.., +64)            : pack centers into B-fragment order (fp16)
//   [.., +576)           : pack W into B-fragment order (fp16)
//   [.., +1088)          : row squared norms (x then centers)
#define NB_BIAS 16
#define NB_PX  (NB_BIAS + 1024)
#define NB_PC  (NB_PX + 64)
#define NB_PW  (NB_PC + 576)
#define NB_SQ  (NB_PW + 1088)
#define NB_ALL NB_SQ

__global__ void __launch_bounds__(256) k_prep_all(const float* __restrict__ x,
                                                  const float* __restrict__ cen,
                                                  const float* __restrict__ w) {
    const int b   = blockIdx.x;
    const int tid = threadIdx.x;

    if (b < NB_BIAS) {
        // ---- bias partial: centers [32b, 32b+32), coalesced across tid ----
        if (b == 0 && tid == 0) { g_minmax[0] = 0x7f800000u; g_minmax[1] = 0u; }
        float s = 0.f;
        const float* wp = w + (size_t)(b * 32) * (NORD * F_) + tid;
        #pragma unroll
        for (int c = 0; c < 32; c++)
            s += wp[(size_t)c * (NORD * F_)];
        g_bias_part[b][tid] = s;
    } else if (b < NB_PX) {
        // ---- pack x ----
        int gid  = (b - NB_BIAS) * 256 + tid;    // (mi*16+kt)*32+lane
        int lane = gid & 31;
        int kt   = (gid >> 5) & 15;
        int mi   = gid >> 9;
        int c0 = lane & 3, lr = lane >> 2;
        const float* px = x + (size_t)(mi * 16 + lr) * D_ + kt * 16 + 2 * c0;
        float2 v0 = *(const float2*)(px);
        float2 v1 = *(const float2*)(px + 8 * D_);
        float2 v2 = *(const float2*)(px + 8);
        float2 v3 = *(const float2*)(px + 8 * D_ + 8);
        g_xf[gid] = make_uint4(pack_h(v0.x, v0.y), pack_h(v1.x, v1.y),
                               pack_h(v2.x, v2.y), pack_h(v3.x, v3.y));
    } else if (b < NB_PC) {
        // ---- pack centers ----
        int gid  = (b - NB_PX) * 256 + tid;      // (ni*16+kt)*32+lane
        int lane = gid & 31;
        int kt   = (gid >> 5) & 15;
        int ni   = gid >> 9;
        int c0 = lane & 3, lr = lane >> 2;
        const float* pc = cen + (size_t)(ni * 16 + lr) * D_ + kt * 16 + 2 * c0;
        float2 v0 = *(const float2*)(pc);
        float2 v1 = *(const float2*)(pc + 8);
        float2 v2 = *(const float2*)(pc + 8 * D_);
        float2 v3 = *(const float2*)(pc + 8 * D_ + 8);
        g_cf[gid] = make_uint4(pack_h(v0.x, v0.y), pack_h(v1.x, v1.y),
                               pack_h(v2.x, v2.y), pack_h(v3.x, v3.y));
    } else if (b < NB_PW) {
        // ---- pack W ----
        const int idx  = b - NB_PC;
        const int cb   = idx & 31;
        const int fb   = (idx >> 5) & 1;
        const int kt   = idx >> 6;         // 0..8
        const int lane = tid & 31;
        const int n16  = tid >> 5;         // 0..7
        const int c0   = lane & 3;
        const int fr   = lane >> 2;
        const int f0   = fb * 128 + n16 * 16 + fr;
        const int ci0  = cb * 16 + 2 * c0;
        float v[2][4];
        #pragma unroll
        for (int e = 0; e < 2; e++) {
            v[e][0] = w[((size_t)(ci0 + 0) * NORD + kt) * F_ + f0 + e * 8];
            v[e][1] = w[((size_t)(ci0 + 1) * NORD + kt) * F_ + f0 + e * 8];
            v[e][2] = w[((size_t)(ci0 + 8) * NORD + kt) * F_ + f0 + e * 8];
            v[e][3] = w[((size_t)(ci0 + 9) * NORD + kt) * F_ + f0 + e * 8];
        }
        g_wf[(((size_t)(fb * 32 + cb) * NORD + kt) * 8 + n16) * 32 + lane] =
            make_uint4(pack_h(v[0][0], v[0][1]), pack_h(v[0][2], v[0][3]),
                       pack_h(v[1][0], v[1][1]), pack_h(v[1][2], v[1][3]));
    } else {
        // ---- row squared norms ----
        int warp = (b - NB_PW) * 8 + (tid >> 5);
        int lane = tid & 31;
        if (warp >= B_ + C_) return;
        const float* src;
        float* dst;
        if (warp < B_) { src = x   + (size_t)warp * D_;        dst = &g_x2[warp]; }
        else           { src = cen + (size_t)(warp - B_) * D_; dst = &g_c2[warp - B_]; }
        float s = 0.f;
        const float4* p = (const float4*)src;
        #pragma unroll
        for (int i = lane; i < D_ / 4; i += 32) {
            float4 v = p[i];
            s += v.x * v.x + v.y * v.y + v.z * v.z + v.w * v.w;
        }
        #pragma unroll
        for (int o = 16; o > 0; o >>= 1) s += __shfl_xor_sync(0xffffffffu, s, o);
        if (lane == 0) *dst = s;
    }
}

// ---------------- kernel 4: tensorized distance GEMM + min/max ------------
// 128 CTAs (one wave), each computes 2 m-tiles of 128 rows.
__global__ void __launch_bounds__(256) k_dist_mma() {
    __shared__ unsigned int s_min, s_max;
    const int tid  = threadIdx.x;
    const int wid  = tid >> 5;
    const int lane = tid & 31;
    const int wm   = wid & 3;
    const int wn   = wid >> 2;
    const int n0   = blockIdx.x * 128;
    const int tig  = lane & 3;
    const int lr   = lane >> 2;

    if (tid == 0) { s_min = 0x7f800000u; s_max = 0u; }

    float lmin = 3.4e38f, lmax = 0.f;

    for (int mb = 0; mb < 2; mb++) {
        const int m0 = (blockIdx.y * 2 + mb) * 128;

        float acc[2][8][4];
        #pragma unroll
        for (int mt = 0; mt < 2; mt++)
            #pragma unroll
            for (int j = 0; j < 8; j++)
                #pragma unroll
                for (int e = 0; e < 4; e++) acc[mt][j][e] = 0.0f;

        const int mi0 = (m0 >> 4) + wm * 2;
        const int ni0 = (n0 >> 4) + wn * 4;

        #pragma unroll 4
        for (int kt = 0; kt < 16; kt++) {
            uint4 a[2], b[4];
            #pragma unroll
            for (int mt = 0; mt < 2; mt++)
                a[mt] = g_xf[(size_t)((mi0 + mt) * 16 + kt) * 32 + lane];
            #pragma unroll
            for (int g = 0; g < 4; g++)
                b[g] = g_cf[(size_t)((ni0 + g) * 16 + kt) * 32 + lane];
            #pragma unroll
            for (int g = 0; g < 4; g++)
                #pragma unroll
                for (int mt = 0; mt < 2; mt++) {
                    mma_fp16(acc[mt][g * 2 + 0], (const uint32_t*)&a[mt], b[g].x, b[g].y);
                    mma_fp16(acc[mt][g * 2 + 1], (const uint32_t*)&a[mt], b[g].z, b[g].w);
                }
        }

        // epilogue: distances + min/max
        float x2r[2][2];
        #pragma unroll
        for (int mt = 0; mt < 2; mt++)
            #pragma unroll
            for (int rh = 0; rh < 2; rh++)
                x2r[mt][rh] = g_x2[m0 + wm * 32 + mt * 16 + rh * 8 + lr];

        #pragma unroll
        for (int mt = 0; mt < 2; mt++) {
            #pragma unroll
            for (int j = 0; j < 8; j++) {
                const int n = n0 + wn * 64 + j * 8 + tig * 2;
                float2 c2v = *(const float2*)&g_c2[n];
                #pragma unroll
                for (int rh = 0; rh < 2; rh++) {
                    float xx = x2r[mt][rh];
                    float d0 = sqrtf(fmaxf(xx + c2v.x - 2.0f * acc[mt][j][rh * 2 + 0], 0.f));
                    float d1 = sqrtf(fmaxf(xx + c2v.y - 2.0f * acc[mt][j][rh * 2 + 1], 0.f));
                    lmin = fminf(lmin, fminf(d0, d1));
                    lmax = fmaxf(lmax, fmaxf(d0, d1));
                    const int row = m0 + wm * 32 + mt * 16 + rh * 8 + lr;
                    *(float2*)&g_dist[(size_t)row * C_ + n] = make_float2(d0, d1);
                }
            }
        }
    }

    #pragma unroll
    for (int o = 16; o > 0; o >>= 1) {
        lmin = fminf(lmin, __shfl_xor_sync(0xffffffffu, lmin, o));
        lmax = fmaxf(lmax, __shfl_xor_sync(0xffffffffu, lmax, o));
    }
    __syncthreads();
    if (lane == 0) {
        atomicMin(&s_min, __float_as_uint(lmin));
        atomicMax(&s_max, __float_as_uint(lmax));
    }
    __syncthreads();
    if (tid == 0) {
        atomicMin(&g_minmax[0], s_min);
        atomicMax(&g_minmax[1], s_max);
    }
}

// ---------------- kernel 5: register-resident fp16 fragment GEMM -----------
// CTA tile 128x128 with 512 threads / 16 warps (warp tile 16x64) -> 4
// warps/SMSP at 1 CTA/SM; total ALU / MMA / memory identical to the 256-thr
// version, per-warp work halved.
// A = Legendre basis single fp16 (recurrence fp32), B = W single fp16.
// kt=0 (P0==1) folded into exact fp32 bias; GEMM runs orders 1..8 only.

__global__ void __launch_bounds__(512, 1) k_out_frag(float* __restrict__ out) {
    const int tid  = threadIdx.x;
    const int wid  = tid >> 5;
    const int lane = tid & 31;
    const int wm   = wid & 7;     // 8 m-subtiles of 16 rows
    const int wn   = wid >> 3;    // 2 f-subtiles of 64
    const int m0   = blockIdx.y * 128;
    const int f0   = blockIdx.x * 128;
    const int fb   = blockIdx.x;
    const int c0   = lane & 3;
    const int lr   = lane >> 2;

    const float dmin  = __uint_as_float(g_minmax[0]);
    const float dmax  = __uint_as_float(g_minmax[1]);
    const float scale = 2.0f / (dmax - dmin);
    const float tc    = fmaf(-dmin, scale, -1.0f);

    // this thread's 2 m rows (r0 = base, r1 = base + 8)
    const float* dp[2];
    #pragma unroll
    for (int q = 0; q < 2; q++) {
        int row = m0 + wm * 16 + q * 8 + lr;
        dp[q] = g_dist + (size_t)row * C_ + 2 * c0;
    }

    // record = 16B; strides: g:512B, kt:4096B, cb:36864B
    const char* wfb = (const char*)g_wf
        + ((size_t)(fb * 32) * NORD * 8 + wn * 4) * 512 + lane * 16;

    // init accumulators with the exact P0 bias (sum of 16 partials)
    float acc[8][4];
    #pragma unroll
    for (int j = 0; j < 8; j++) {
        const int fz = f0 + wn * 64 + j * 8 + (lane & 3) * 2;
        float2 bz = make_float2(0.f, 0.f);
        #pragma unroll
        for (int p = 0; p < 16; p++) {
            float2 v = *(const float2*)&g_bias_part[p][fz];
            bz.x += v.x;
            bz.y += v.y;
        }
        acc[j][0] = bz.x; acc[j][1] = bz.y;
        acc[j][2] = bz.x; acc[j][3] = bz.y;
    }

    for (int cb = 0; cb < 32; cb++) {
        // t layout: [q*4 + c], q = row half (0: r0, 1: r1),
        //           c = 0,1 -> k 2c0,2c0+1 ; c = 2,3 -> k 2c0+8,2c0+9
        float t[8], pa[8], pb[8];
        #pragma unroll
        for (int q = 0; q < 2; q++) {
            float2 a0 = *(const float2*)(dp[q] + cb * 16);
            float2 a1 = *(const float2*)(dp[q] + cb * 16 + 8);
            t[q * 4 + 0] = fmaf(a0.x, scale, tc);
            t[q * 4 + 1] = fmaf(a0.y, scale, tc);
            t[q * 4 + 2] = fmaf(a1.x, scale, tc);
            t[q * 4 + 3] = fmaf(a1.y, scale, tc);
        }
        #pragma unroll
        for (int i = 0; i < 8; i++) { pa[i] = 1.0f; pb[i] = t[i]; }

        const char* wpc = wfb + (size_t)cb * (NORD * 8 * 512);

        #pragma unroll
        for (int kt = 1; kt < NORD; kt++) {
            // ---- B fragments for all 4 n16-groups of this kt ----
            const char* wpt = wpc + (size_t)kt * 4096;
            uint4 b[4];
            #pragma unroll
            for (int g = 0; g < 4; g++)
                b[g] = *(const uint4*)(wpt + g * 512);

            // ---- A fragment for order kt (single fp16) ----
            uint32_t ah[4];
            if (kt >= 2) {
                const float an = (2.0f * kt - 1.0f) / (float)kt;
                const float bn = (float)(kt - 1) / (float)kt;
                #pragma unroll
                for (int i = 0; i < 8; i++) {
                    float p2 = an * t[i] * pb[i] - bn * pa[i];
                    pa[i] = pb[i];
                    pb[i] = p2;
                }
            }
            ah[0] = pack_h(pb[0], pb[1]);   // row r0, k01
            ah[1] = pack_h(pb[4], pb[5]);   // row r1, k01
            ah[2] = pack_h(pb[2], pb[3]);   // row r0, k89
            ah[3] = pack_h(pb[6], pb[7]);   // row r1, k89

            // 8 independent mmas
            #pragma unroll
            for (int g = 0; g < 4; g++) {
                mma_fp16(acc[g * 2 + 0], ah, b[g].x, b[g].y);
                mma_fp16(acc[g * 2 + 1], ah, b[g].z, b[g].w);
            }
        }
    }

    // epilogue
    {
        const int g   = lane >> 2;
        const int tig = lane & 3;
        const int mb  = m0 + wm * 16;
        #pragma unroll
        for (int j = 0; j < 8; j++) {
            const int f = f0 + wn * 64 + j * 8 + tig * 2;
            float2 lo = make_float2(acc[j][0], acc[j][1]);
            float2 hi = make_float2(acc[j][2], acc[j][3]);
            *(float2*)(out + (size_t)(mb + g)     * F_ + f) = lo;
            *(float2*)(out + (size_t)(mb + g + 8) * F_ + f) = hi;
        }
    }
}

// ---------------- launch ---------------------------------------------------
extern "C" void kernel_launch(void* const* d_in, const int* in_sizes, int n_in,
                              void* d_out, int out_size) {
    const float* x   = (const float*)d_in[0];   // [8192,256]
    const float* cen = (const float*)d_in[1];   // [512,256]
    const float* w   = (const float*)d_in[2];   // [512,9,256]
    float* out = (float*)d_out;                 // [8192,256]

    k_prep_all<<<NB_ALL, 256>>>(x, cen, w);
    k_dist_mma<<<dim3(C_ / 128, B_ / 256), 256>>>();
    k_out_frag<<<dim3(F_ / 128, B_ / 128), 512>>>(out);
}

// round 13
// speedup vs baseline: 1.2031x; 1.0391x over previous
#include <cuda_runtime.h>
#include <cuda_fp16.h>
#include <cstdint>

// Problem constants (fixed by reference)
#define B_   8192   // batch
#define D_   256    // input dim
#define C_   512    // num centers
#define NORD 9      // order+1
#define F_   256    // output dim
#define KTOT (C_ * NORD)   // 4608

// ---------------- scratch (static device globals; no allocation) ----------
__device__ __align__(16) float g_dist[(size_t)B_ * C_];   // 16 MB
__device__ float g_x2[B_];
__device__ float g_c2[C_];
__device__ float g_bias_part[16][F_];
__device__ unsigned int g_minmax[2];
// W packed in mma-fragment order, single fp16 (record = 16B uint4)
__device__ __align__(16) uint4 g_wf[2 * 32 * NORD * 8 * 32];   // 2.4 MB
// x packed in A-fragment order, single fp16: [mi(512)][kt(16)][lane(32)]
__device__ __align__(16) uint4 g_xf[(B_ / 16) * 16 * 32];      // 4 MB
// centers packed in B-fragment order, single fp16
__device__ __align__(16) uint4 g_cf[(C_ / 16) * 16 * 32];      // 256 KB

// ==================== small helpers ========================================
__device__ __forceinline__ void mma_fp16(float* d, const uint32_t* a,
                                         uint32_t b0, uint32_t b1) {
    asm volatile(
        "mma.sync.aligned.m16n8k16.row.col.f32.f16.f16.f32 "
        "{%0,%1,%2,%3}, {%4,%5,%6,%7}, {%8,%9}, {%0,%1,%2,%3};"
        : "+f"(d[0]), "+f"(d[1]), "+f"(d[2]), "+f"(d[3])
        : "r"(a[0]), "r"(a[1]), "r"(a[2]), "r"(a[3]), "r"(b0), "r"(b1));
}

__device__ __forceinline__ uint32_t pack_h(float v0, float v1) {
    __half2 h = __floats2half2_rn(v0, v1);
    return *(uint32_t*)&h;
}

// ---- packed f32x2 helpers (sm_100+ PTX; 2 fp32 lanes per instruction) ----
__device__ __forceinline__ uint64_t f2_pack(float lo, float hi) {
    uint64_t r;
    asm("mov.b64 %0, {%1, %2};" : "=l"(r) : "f"(lo), "f"(hi));
    return r;
}
__device__ __forceinline__ uint64_t f2_mul(uint64_t a, uint64_t b) {
    uint64_t r;
    asm("mul.rn.f32x2 %0, %1, %2;" : "=l"(r) : "l"(a), "l"(b));
    return r;
}
__device__ __forceinline__ uint64_t f2_fma(uint64_t a, uint64_t b, uint64_t c) {
    uint64_t r;
    asm("fma.rn.f32x2 %0, %1, %2, %3;" : "=l"(r) : "l"(a), "l"(b), "l"(c));
    return r;
}
// packed (lo,hi) f32 pair -> f16x2 {lo, hi}
__device__ __forceinline__ uint32_t f2_to_h2(uint64_t p) {
    uint32_t r;
    asm("{\n\t.reg .f32 lo, hi;\n\t"
        "mov.b64 {lo, hi}, %1;\n\t"
        "cvt.rn.f16x2.f32 %0, hi, lo;\n\t}"
        : "=r"(r) : "l"(p));
    return r;
}

// ---------------- fused prep kernel ----------------------------------------
#define NB_BIAS 16
#define NB_PX  (NB_BIAS + 1024)
#define NB_PC  (NB_PX + 64)
#define NB_PW  (NB_PC + 576)
#define NB_SQ  (NB_PW + 1088)
#define NB_ALL NB_SQ

__global__ void __launch_bounds__(256) k_prep_all(const float* __restrict__ x,
                                                  const float* __restrict__ cen,
                                                  const float* __restrict__ w) {
    const int b   = blockIdx.x;
    const int tid = threadIdx.x;

    if (b < NB_BIAS) {
        if (b == 0 && tid == 0) { g_minmax[0] = 0x7f800000u; g_minmax[1] = 0u; }
        float s = 0.f;
        const float* wp = w + (size_t)(b * 32) * (NORD * F_) + tid;
        #pragma unroll
        for (int c = 0; c < 32; c++)
            s += wp[(size_t)c * (NORD * F_)];
        g_bias_part[b][tid] = s;
    } else if (b < NB_PX) {
        int gid  = (b - NB_BIAS) * 256 + tid;
        int lane = gid & 31;
        int kt   = (gid >> 5) & 15;
        int mi   = gid >> 9;
        int c0 = lane & 3, lr = lane >> 2;
        const float* px = x + (size_t)(mi * 16 + lr) * D_ + kt * 16 + 2 * c0;
        float2 v0 = *(const float2*)(px);
        float2 v1 = *(const float2*)(px + 8 * D_);
        float2 v2 = *(const float2*)(px + 8);
        float2 v3 = *(const float2*)(px + 8 * D_ + 8);
        g_xf[gid] = make_uint4(pack_h(v0.x, v0.y), pack_h(v1.x, v1.y),
                               pack_h(v2.x, v2.y), pack_h(v3.x, v3.y));
    } else if (b < NB_PC) {
        int gid  = (b - NB_PX) * 256 + tid;
        int lane = gid & 31;
        int kt   = (gid >> 5) & 15;
        int ni   = gid >> 9;
        int c0 = lane & 3, lr = lane >> 2;
        const float* pc = cen + (size_t)(ni * 16 + lr) * D_ + kt * 16 + 2 * c0;
        float2 v0 = *(const float2*)(pc);
        float2 v1 = *(const float2*)(pc + 8);
        float2 v2 = *(const float2*)(pc + 8 * D_);
        float2 v3 = *(const float2*)(pc + 8 * D_ + 8);
        g_cf[gid] = make_uint4(pack_h(v0.x, v0.y), pack_h(v1.x, v1.y),
                               pack_h(v2.x, v2.y), pack_h(v3.x, v3.y));
    } else if (b < NB_PW) {
        const int idx  = b - NB_PC;
        const int cb   = idx & 31;
        const int fb   = (idx >> 5) & 1;
        const int kt   = idx >> 6;
        const int lane = tid & 31;
        const int n16  = tid >> 5;
        const int c0   = lane & 3;
        const int fr   = lane >> 2;
        const int f0   = fb * 128 + n16 * 16 + fr;
        const int ci0  = cb * 16 + 2 * c0;
        float v[2][4];
        #pragma unroll
        for (int e = 0; e < 2; e++) {
            v[e][0] = w[((size_t)(ci0 + 0) * NORD + kt) * F_ + f0 + e * 8];
            v[e][1] = w[((size_t)(ci0 + 1) * NORD + kt) * F_ + f0 + e * 8];
            v[e][2] = w[((size_t)(ci0 + 8) * NORD + kt) * F_ + f0 + e * 8];
            v[e][3] = w[((size_t)(ci0 + 9) * NORD + kt) * F_ + f0 + e * 8];
        }
        g_wf[(((size_t)(fb * 32 + cb) * NORD + kt) * 8 + n16) * 32 + lane] =
            make_uint4(pack_h(v[0][0], v[0][1]), pack_h(v[0][2], v[0][3]),
                       pack_h(v[1][0], v[1][1]), pack_h(v[1][2], v[1][3]));
    } else {
        int warp = (b - NB_PW) * 8 + (tid >> 5);
        int lane = tid & 31;
        if (warp >= B_ + C_) return;
        const float* src;
        float* dst;
        if (warp < B_) { src = x   + (size_t)warp * D_;        dst = &g_x2[warp]; }
        else           { src = cen + (size_t)(warp - B_) * D_; dst = &g_c2[warp - B_]; }
        float s = 0.f;
        const float4* p = (const float4*)src;
        #pragma unroll
        for (int i = lane; i < D_ / 4; i += 32) {
            float4 v = p[i];
            s += v.x * v.x + v.y * v.y + v.z * v.z + v.w * v.w;
        }
        #pragma unroll
        for (int o = 16; o > 0; o >>= 1) s += __shfl_xor_sync(0xffffffffu, s, o);
        if (lane == 0) *dst = s;
    }
}

// ---------------- kernel 4: tensorized distance GEMM + min/max ------------
// R10 shape: grid (4, 64) = 256 CTAs, CTA tile 128x128.
__global__ void __launch_bounds__(256) k_dist_mma() {
    __shared__ unsigned int s_min, s_max;
    const int tid  = threadIdx.x;
    const int wid  = tid >> 5;
    const int lane = tid & 31;
    const int wm   = wid & 3;
    const int wn   = wid >> 2;
    const int m0   = blockIdx.y * 128;
    const int n0   = blockIdx.x * 128;
    const int tig  = lane & 3;
    const int lr   = lane >> 2;

    if (tid == 0) { s_min = 0x7f800000u; s_max = 0u; }

    float acc[2][8][4];
    #pragma unroll
    for (int mt = 0; mt < 2; mt++)
        #pragma unroll
        for (int j = 0; j < 8; j++)
            #pragma unroll
            for (int e = 0; e < 4; e++) acc[mt][j][e] = 0.0f;

    const int mi0 = (m0 >> 4) + wm * 2;
    const int ni0 = (n0 >> 4) + wn * 4;

    #pragma unroll 4
    for (int kt = 0; kt < 16; kt++) {
        uint4 a[2], b[4];
        #pragma unroll
        for (int mt = 0; mt < 2; mt++)
            a[mt] = g_xf[(size_t)((mi0 + mt) * 16 + kt) * 32 + lane];
        #pragma unroll
        for (int g = 0; g < 4; g++)
            b[g] = g_cf[(size_t)((ni0 + g) * 16 + kt) * 32 + lane];
        #pragma unroll
        for (int g = 0; g < 4; g++)
            #pragma unroll
            for (int mt = 0; mt < 2; mt++) {
                mma_fp16(acc[mt][g * 2 + 0], (const uint32_t*)&a[mt], b[g].x, b[g].y);
                mma_fp16(acc[mt][g * 2 + 1], (const uint32_t*)&a[mt], b[g].z, b[g].w);
            }
    }

    float x2r[2][2];
    #pragma unroll
    for (int mt = 0; mt < 2; mt++)
        #pragma unroll
        for (int rh = 0; rh < 2; rh++)
            x2r[mt][rh] = g_x2[m0 + wm * 32 + mt * 16 + rh * 8 + lr];

    float lmin = 3.4e38f, lmax = 0.f;
    #pragma unroll
    for (int mt = 0; mt < 2; mt++) {
        #pragma unroll
        for (int j = 0; j < 8; j++) {
            const int n = n0 + wn * 64 + j * 8 + tig * 2;
            float2 c2v = *(const float2*)&g_c2[n];
            #pragma unroll
            for (int rh = 0; rh < 2; rh++) {
                float xx = x2r[mt][rh];
                float d0 = sqrtf(fmaxf(xx + c2v.x - 2.0f * acc[mt][j][rh * 2 + 0], 0.f));
                float d1 = sqrtf(fmaxf(xx + c2v.y - 2.0f * acc[mt][j][rh * 2 + 1], 0.f));
                lmin = fminf(lmin, fminf(d0, d1));
                lmax = fmaxf(lmax, fmaxf(d0, d1));
                const int row = m0 + wm * 32 + mt * 16 + rh * 8 + lr;
                *(float2*)&g_dist[(size_t)row * C_ + n] = make_float2(d0, d1);
            }
        }
    }

    #pragma unroll
    for (int o = 16; o > 0; o >>= 1) {
        lmin = fminf(lmin, __shfl_xor_sync(0xffffffffu, lmin, o));
        lmax = fmaxf(lmax, __shfl_xor_sync(0xffffffffu, lmax, o));
    }
    __syncthreads();
    if (lane == 0) {
        atomicMin(&s_min, __float_as_uint(lmin));
        atomicMax(&s_max, __float_as_uint(lmax));
    }
    __syncthreads();
    if (tid == 0) {
        atomicMin(&g_minmax[0], s_min);
        atomicMax(&g_minmax[1], s_max);
    }
}

// ---------------- kernel 5: fp16 fragment GEMM, f32x2 recurrence -----------
// R10 shape: CTA 128x128, 256 threads, grid (2, 64). Legendre recurrence in
// packed f32x2 (2 lanes/instr, identical fp32 rounding per lane).
// Pair index p = q*2 + h, q = mt*2 + r (row), h = k-half; pair = (c, c+1).

__global__ void __launch_bounds__(256, 1) k_out_frag(float* __restrict__ out) {
    const int tid  = threadIdx.x;
    const int wid  = tid >> 5;
    const int lane = tid & 31;
    const int wm   = wid & 3;
    const int wn   = wid >> 2;
    const int m0   = blockIdx.y * 128;
    const int f0   = blockIdx.x * 128;
    const int fb   = blockIdx.x;
    const int c0   = lane & 3;
    const int lr   = lane >> 2;

    const float dmin  = __uint_as_float(g_minmax[0]);
    const float dmax  = __uint_as_float(g_minmax[1]);
    const float scale = 2.0f / (dmax - dmin);
    const float tc    = fmaf(-dmin, scale, -1.0f);
    const uint64_t scale2 = f2_pack(scale, scale);
    const uint64_t tc2    = f2_pack(tc, tc);

    const float* dp[4];
    #pragma unroll
    for (int q = 0; q < 4; q++) {
        int row = m0 + wm * 32 + (q >> 1) * 16 + (q & 1) * 8 + lr;
        dp[q] = g_dist + (size_t)row * C_ + 2 * c0;
    }

    // record = 16B; strides: g:512B, kt:4096B, cb:36864B
    const char* wfb = (const char*)g_wf
        + ((size_t)(fb * 32) * NORD * 8 + wn * 4) * 512 + lane * 16;

    // init accumulators with the exact P0 bias (sum of 16 partials)
    float acc[2][8][4];
    #pragma unroll
    for (int j = 0; j < 8; j++) {
        const int fz = f0 + wn * 64 + j * 8 + (lane & 3) * 2;
        float2 bz = make_float2(0.f, 0.f);
        #pragma unroll
        for (int p = 0; p < 16; p++) {
            float2 v = *(const float2*)&g_bias_part[p][fz];
            bz.x += v.x;
            bz.y += v.y;
        }
        #pragma unroll
        for (int mt = 0; mt < 2; mt++) {
            acc[mt][j][0] = bz.x; acc[mt][j][1] = bz.y;
            acc[mt][j][2] = bz.x; acc[mt][j][3] = bz.y;
        }
    }

    // prefetched packed distance pairs for current chunk: dv[q*2+h]
    uint64_t dv[8];
    #pragma unroll
    for (int q = 0; q < 4; q++) {
        dv[q * 2 + 0] = *(const uint64_t*)(dp[q]);
        dv[q * 2 + 1] = *(const uint64_t*)(dp[q] + 8);
    }

    for (int cb = 0; cb < 32; cb++) {
        uint64_t tP[8], pa[8], pb[8];
        #pragma unroll
        for (int i = 0; i < 8; i++)
            tP[i] = f2_fma(dv[i], scale2, tc2);
        if (cb < 31) {
            #pragma unroll
            for (int q = 0; q < 4; q++) {
                dv[q * 2 + 0] = *(const uint64_t*)(dp[q] + (cb + 1) * 16);
                dv[q * 2 + 1] = *(const uint64_t*)(dp[q] + (cb + 1) * 16 + 8);
            }
        }
        const uint64_t one2 = f2_pack(1.0f, 1.0f);
        #pragma unroll
        for (int i = 0; i < 8; i++) { pa[i] = one2; pb[i] = tP[i]; }

        const char* wpc = wfb + (size_t)cb * (NORD * 8 * 512);

        #pragma unroll
        for (int kt = 1; kt < NORD; kt++) {
            // ---- B fragments for all 4 n16-groups of this kt ----
            const char* wpt = wpc + (size_t)kt * 4096;
            uint4 b[4];
            #pragma unroll
            for (int g = 0; g < 4; g++)
                b[g] = *(const uint4*)(wpt + g * 512);

            // ---- A fragments for order kt (f32x2 recurrence) ----
            uint32_t ah[2][4];
            if (kt >= 2) {
                const float an = (2.0f * kt - 1.0f) / (float)kt;
                const float bn = (float)(kt - 1) / (float)kt;
                const uint64_t an2  = f2_pack(an, an);
                const uint64_t nbn2 = f2_pack(-bn, -bn);
                #pragma unroll
                for (int i = 0; i < 8; i++) {
                    uint64_t p2 = f2_fma(an2, f2_mul(tP[i], pb[i]),
                                         f2_mul(nbn2, pa[i]));
                    pa[i] = pb[i];
                    pb[i] = p2;
                }
            }
            #pragma unroll
            for (int mt = 0; mt < 2; mt++) {
                ah[mt][0] = f2_to_h2(pb[(mt * 2 + 0) * 2 + 0]);
                ah[mt][1] = f2_to_h2(pb[(mt * 2 + 1) * 2 + 0]);
                ah[mt][2] = f2_to_h2(pb[(mt * 2 + 0) * 2 + 1]);
                ah[mt][3] = f2_to_h2(pb[(mt * 2 + 1) * 2 + 1]);
            }

            // 16 independent mmas
            #pragma unroll
            for (int g = 0; g < 4; g++)
                #pragma unroll
                for (int mt = 0; mt < 2; mt++) {
                    mma_fp16(acc[mt][g * 2 + 0], ah[mt], b[g].x, b[g].y);
                    mma_fp16(acc[mt][g * 2 + 1], ah[mt], b[g].z, b[g].w);
                }
        }
    }

    // epilogue
    {
        const int g   = lane >> 2;
        const int tig = lane & 3;
        #pragma unroll
        for (int mt = 0; mt < 2; mt++) {
            const int mb = m0 + wm * 32 + mt * 16;
            #pragma unroll
            for (int j = 0; j < 8; j++) {
                const int f = f0 + wn * 64 + j * 8 + tig * 2;
                float2 lo = make_float2(acc[mt][j][0], acc[mt][j][1]);
                float2 hi = make_float2(acc[mt][j][2], acc[mt][j][3]);
                *(float2*)(out + (size_t)(mb + g)     * F_ + f) = lo;
                *(float2*)(out + (size_t)(mb + g + 8) * F_ + f) = hi;
            }
        }
    }
}

// ---------------- launch ---------------------------------------------------
extern "C" void kernel_launch(void* const* d_in, const int* in_sizes, int n_in,
                              void* d_out, int out_size) {
    const float* x   = (const float*)d_in[0];   // [8192,256]
    const float* cen = (const float*)d_in[1];   // [512,256]
    const float* w   = (const float*)d_in[2];   // [512,9,256]
    float* out = (float*)d_out;                 // [8192,256]

    k_prep_all<<<NB_ALL, 256>>>(x, cen, w);
    k_dist_mma<<<dim3(C_ / 128, B_ / 128), 256>>>();
    k_out_frag<<<dim3(F_ / 128, B_ / 128), 256>>>(out);
}

// round 14
// speedup vs baseline: 1.2257x; 1.0187x over previous
#include <cuda_runtime.h>
#include <cuda_fp16.h>
#include <cstdint>

// Problem constants (fixed by reference)
#define B_   8192   // batch
#define D_   256    // input dim
#define C_   512    // num centers
#define NORD 9      // order+1
#define F_   256    // output dim
#define KTOT (C_ * NORD)   // 4608

// ---------------- scratch (static device globals; no allocation) ----------
__device__ __align__(16) float g_dist[(size_t)B_ * C_];   // 16 MB
__device__ float g_x2[B_];
__device__ float g_c2[C_];
__device__ float g_bias_part[16][F_];
__device__ unsigned int g_minmax[2];
__device__ unsigned int g_bar;
// W packed in mma-fragment order, single fp16 (record = 16B uint4)
__device__ __align__(16) uint4 g_wf[2 * 32 * NORD * 8 * 32];   // 2.4 MB
// x packed in A-fragment order, single fp16: [mi(512)][kt(16)][lane(32)]
__device__ __align__(16) uint4 g_xf[(B_ / 16) * 16 * 32];      // 4 MB
// centers packed in B-fragment order, single fp16
__device__ __align__(16) uint4 g_cf[(C_ / 16) * 16 * 32];      // 256 KB

#define GRID_MAIN 128

// ==================== small helpers ========================================
__device__ __forceinline__ void mma_fp16(float* d, const uint32_t* a,
                                         uint32_t b0, uint32_t b1) {
    asm volatile(
        "mma.sync.aligned.m16n8k16.row.col.f32.f16.f16.f32 "
        "{%0,%1,%2,%3}, {%4,%5,%6,%7}, {%8,%9}, {%0,%1,%2,%3};"
        : "+f"(d[0]), "+f"(d[1]), "+f"(d[2]), "+f"(d[3])
        : "r"(a[0]), "r"(a[1]), "r"(a[2]), "r"(a[3]), "r"(b0), "r"(b1));
}

__device__ __forceinline__ uint32_t pack_h(float v0, float v1) {
    __half2 h = __floats2half2_rn(v0, v1);
    return *(uint32_t*)&h;
}

// ---------------- fused prep kernel ----------------------------------------
#define NB_BIAS 16
#define NB_PX  (NB_BIAS + 1024)
#define NB_PC  (NB_PX + 64)
#define NB_PW  (NB_PC + 576)
#define NB_SQ  (NB_PW + 1088)
#define NB_ALL NB_SQ

__global__ void __launch_bounds__(256) k_prep_all(const float* __restrict__ x,
                                                  const float* __restrict__ cen,
                                                  const float* __restrict__ w) {
    const int b   = blockIdx.x;
    const int tid = threadIdx.x;

    if (b < NB_BIAS) {
        if (b == 0 && tid == 0) {
            g_minmax[0] = 0x7f800000u;
            g_minmax[1] = 0u;
            g_bar = 0u;
        }
        float s = 0.f;
        const float* wp = w + (size_t)(b * 32) * (NORD * F_) + tid;
        #pragma unroll
        for (int c = 0; c < 32; c++)
            s += wp[(size_t)c * (NORD * F_)];
        g_bias_part[b][tid] = s;
    } else if (b < NB_PX) {
        int gid  = (b - NB_BIAS) * 256 + tid;
        int lane = gid & 31;
        int kt   = (gid >> 5) & 15;
        int mi   = gid >> 9;
        int c0 = lane & 3, lr = lane >> 2;
        const float* px = x + (size_t)(mi * 16 + lr) * D_ + kt * 16 + 2 * c0;
        float2 v0 = *(const float2*)(px);
        float2 v1 = *(const float2*)(px + 8 * D_);
        float2 v2 = *(const float2*)(px + 8);
        float2 v3 = *(const float2*)(px + 8 * D_ + 8);
        g_xf[gid] = make_uint4(pack_h(v0.x, v0.y), pack_h(v1.x, v1.y),
                               pack_h(v2.x, v2.y), pack_h(v3.x, v3.y));
    } else if (b < NB_PC) {
        int gid  = (b - NB_PX) * 256 + tid;
        int lane = gid & 31;
        int kt   = (gid >> 5) & 15;
        int ni   = gid >> 9;
        int c0 = lane & 3, lr = lane >> 2;
        const float* pc = cen + (size_t)(ni * 16 + lr) * D_ + kt * 16 + 2 * c0;
        float2 v0 = *(const float2*)(pc);
        float2 v1 = *(const float2*)(pc + 8);
        float2 v2 = *(const float2*)(pc + 8 * D_);
        float2 v3 = *(const float2*)(pc + 8 * D_ + 8);
        g_cf[gid] = make_uint4(pack_h(v0.x, v0.y), pack_h(v1.x, v1.y),
                               pack_h(v2.x, v2.y), pack_h(v3.x, v3.y));
    } else if (b < NB_PW) {
        const int idx  = b - NB_PC;
        const int cb   = idx & 31;
        const int fb   = (idx >> 5) & 1;
        const int kt   = idx >> 6;
        const int lane = tid & 31;
        const int n16  = tid >> 5;
        const int c0   = lane & 3;
        const int fr   = lane >> 2;
        const int f0   = fb * 128 + n16 * 16 + fr;
        const int ci0  = cb * 16 + 2 * c0;
        float v[2][4];
        #pragma unroll
        for (int e = 0; e < 2; e++) {
            v[e][0] = w[((size_t)(ci0 + 0) * NORD + kt) * F_ + f0 + e * 8];
            v[e][1] = w[((size_t)(ci0 + 1) * NORD + kt) * F_ + f0 + e * 8];
            v[e][2] = w[((size_t)(ci0 + 8) * NORD + kt) * F_ + f0 + e * 8];
            v[e][3] = w[((size_t)(ci0 + 9) * NORD + kt) * F_ + f0 + e * 8];
        }
        g_wf[(((size_t)(fb * 32 + cb) * NORD + kt) * 8 + n16) * 32 + lane] =
            make_uint4(pack_h(v[0][0], v[0][1]), pack_h(v[0][2], v[0][3]),
                       pack_h(v[1][0], v[1][1]), pack_h(v[1][2], v[1][3]));
    } else {
        int warp = (b - NB_PW) * 8 + (tid >> 5);
        int lane = tid & 31;
        if (warp >= B_ + C_) return;
        const float* src;
        float* dst;
        if (warp < B_) { src = x   + (size_t)warp * D_;        dst = &g_x2[warp]; }
        else           { src = cen + (size_t)(warp - B_) * D_; dst = &g_c2[warp - B_]; }
        float s = 0.f;
        const float4* p = (const float4*)src;
        #pragma unroll
        for (int i = lane; i < D_ / 4; i += 32) {
            float4 v = p[i];
            s += v.x * v.x + v.y * v.y + v.z * v.z + v.w * v.w;
        }
        #pragma unroll
        for (int o = 16; o > 0; o >>= 1) s += __shfl_xor_sync(0xffffffffu, s, o);
        if (lane == 0) *dst = s;
    }
}

// ---------------- fused main kernel: dist phase + barrier + out phase ------
#define IDX(mt, r, c) (((mt) * 2 + (r)) * 4 + (c))

__global__ void __launch_bounds__(256, 1) k_main(float* __restrict__ out) {
    __shared__ unsigned int s_min, s_max;
    const int bx   = blockIdx.x;      // 0..127
    const int tid  = threadIdx.x;
    const int wid  = tid >> 5;
    const int lane = tid & 31;
    const int wm   = wid & 3;
    const int wn   = wid >> 2;
    const int tig  = lane & 3;
    const int lr   = lane >> 2;

    // ==================== phase 1: distance GEMM + min/max =================
    {
        const int n0 = (bx & 3) * 128;
        const int mp = bx >> 2;           // 0..31, two m-tiles each

        if (tid == 0) { s_min = 0x7f800000u; s_max = 0u; }

        float lmin = 3.4e38f, lmax = 0.f;

        for (int mb = 0; mb < 2; mb++) {
            const int m0 = (mp * 2 + mb) * 128;

            float acc[2][8][4];
            #pragma unroll
            for (int mt = 0; mt < 2; mt++)
                #pragma unroll
                for (int j = 0; j < 8; j++)
                    #pragma unroll
                    for (int e = 0; e < 4; e++) acc[mt][j][e] = 0.0f;

            const int mi0 = (m0 >> 4) + wm * 2;
            const int ni0 = (n0 >> 4) + wn * 4;

            #pragma unroll 4
            for (int kt = 0; kt < 16; kt++) {
                uint4 a[2], b[4];
                #pragma unroll
                for (int mt = 0; mt < 2; mt++)
                    a[mt] = g_xf[(size_t)((mi0 + mt) * 16 + kt) * 32 + lane];
                #pragma unroll
                for (int g = 0; g < 4; g++)
                    b[g] = g_cf[(size_t)((ni0 + g) * 16 + kt) * 32 + lane];
                #pragma unroll
                for (int g = 0; g < 4; g++)
                    #pragma unroll
                    for (int mt = 0; mt < 2; mt++) {
                        mma_fp16(acc[mt][g * 2 + 0], (const uint32_t*)&a[mt],
                                 b[g].x, b[g].y);
                        mma_fp16(acc[mt][g * 2 + 1], (const uint32_t*)&a[mt],
                                 b[g].z, b[g].w);
                    }
            }

            float x2r[2][2];
            #pragma unroll
            for (int mt = 0; mt < 2; mt++)
                #pragma unroll
                for (int rh = 0; rh < 2; rh++)
                    x2r[mt][rh] = g_x2[m0 + wm * 32 + mt * 16 + rh * 8 + lr];

            #pragma unroll
            for (int mt = 0; mt < 2; mt++) {
                #pragma unroll
                for (int j = 0; j < 8; j++) {
                    const int n = n0 + wn * 64 + j * 8 + tig * 2;
                    float2 c2v = *(const float2*)&g_c2[n];
                    #pragma unroll
                    for (int rh = 0; rh < 2; rh++) {
                        float xx = x2r[mt][rh];
                        float d0 = sqrtf(fmaxf(xx + c2v.x - 2.0f * acc[mt][j][rh * 2 + 0], 0.f));
                        float d1 = sqrtf(fmaxf(xx + c2v.y - 2.0f * acc[mt][j][rh * 2 + 1], 0.f));
                        lmin = fminf(lmin, fminf(d0, d1));
                        lmax = fmaxf(lmax, fmaxf(d0, d1));
                        const int row = m0 + wm * 32 + mt * 16 + rh * 8 + lr;
                        *(float2*)&g_dist[(size_t)row * C_ + n] = make_float2(d0, d1);
                    }
                }
            }
        }

        #pragma unroll
        for (int o = 16; o > 0; o >>= 1) {
            lmin = fminf(lmin, __shfl_xor_sync(0xffffffffu, lmin, o));
            lmax = fmaxf(lmax, __shfl_xor_sync(0xffffffffu, lmax, o));
        }
        __syncthreads();
        if (lane == 0) {
            atomicMin(&s_min, __float_as_uint(lmin));
            atomicMax(&s_max, __float_as_uint(lmax));
        }
        __syncthreads();
        if (tid == 0) {
            atomicMin(&g_minmax[0], s_min);
            atomicMax(&g_minmax[1], s_max);
        }
    }

    // ==================== grid barrier =====================================
    if (tid == 0) {
        __threadfence();
        atomicAdd(&g_bar, 1u);
        while (atomicAdd(&g_bar, 0u) < GRID_MAIN) __nanosleep(64);
    }
    __syncthreads();

    // ==================== phase 2: output fragment GEMM ====================
    {
        const int fb = bx & 1;
        const int m0 = (bx >> 1) * 128;
        const int f0 = fb * 128;
        const int c0 = tig;

        const float dmin  = __uint_as_float(g_minmax[0]);
        const float dmax  = __uint_as_float(g_minmax[1]);
        const float scale = 2.0f / (dmax - dmin);
        const float tc    = fmaf(-dmin, scale, -1.0f);

        const float* dp[4];
        #pragma unroll
        for (int q = 0; q < 4; q++) {
            int row = m0 + wm * 32 + (q >> 1) * 16 + (q & 1) * 8 + lr;
            dp[q] = g_dist + (size_t)row * C_ + 2 * c0;
        }

        // record = 16B; strides: g:512B, kt:4096B, cb:36864B
        const char* wfb = (const char*)g_wf
            + ((size_t)(fb * 32) * NORD * 8 + wn * 4) * 512 + lane * 16;

        // init accumulators with the exact P0 bias (sum of 16 partials)
        float acc[2][8][4];
        #pragma unroll
        for (int j = 0; j < 8; j++) {
            const int fz = f0 + wn * 64 + j * 8 + tig * 2;
            float2 bz = make_float2(0.f, 0.f);
            #pragma unroll
            for (int p = 0; p < 16; p++) {
                float2 v = *(const float2*)&g_bias_part[p][fz];
                bz.x += v.x;
                bz.y += v.y;
            }
            #pragma unroll
            for (int mt = 0; mt < 2; mt++) {
                acc[mt][j][0] = bz.x; acc[mt][j][1] = bz.y;
                acc[mt][j][2] = bz.x; acc[mt][j][3] = bz.y;
            }
        }

        float2 dv[8];
        #pragma unroll
        for (int q = 0; q < 4; q++) {
            dv[q * 2 + 0] = *(const float2*)(dp[q]);
            dv[q * 2 + 1] = *(const float2*)(dp[q] + 8);
        }

        for (int cb = 0; cb < 32; cb++) {
            float t[16], pa[16], pb[16];
            #pragma unroll
            for (int q = 0; q < 4; q++) {
                t[q * 4 + 0] = fmaf(dv[q * 2 + 0].x, scale, tc);
                t[q * 4 + 1] = fmaf(dv[q * 2 + 0].y, scale, tc);
                t[q * 4 + 2] = fmaf(dv[q * 2 + 1].x, scale, tc);
                t[q * 4 + 3] = fmaf(dv[q * 2 + 1].y, scale, tc);
            }
            if (cb < 31) {
                #pragma unroll
                for (int q = 0; q < 4; q++) {
                    dv[q * 2 + 0] = *(const float2*)(dp[q] + (cb + 1) * 16);
                    dv[q * 2 + 1] = *(const float2*)(dp[q] + (cb + 1) * 16 + 8);
                }
            }
            #pragma unroll
            for (int i = 0; i < 16; i++) { pa[i] = 1.0f; pb[i] = t[i]; }

            const char* wpc = wfb + (size_t)cb * (NORD * 8 * 512);

            #pragma unroll
            for (int kt = 1; kt < NORD; kt++) {
                const char* wpt = wpc + (size_t)kt * 4096;
                uint4 b[4];
                #pragma unroll
                for (int g = 0; g < 4; g++)
                    b[g] = *(const uint4*)(wpt + g * 512);

                uint32_t ah[2][4];
                if (kt >= 2) {
                    const float an = (2.0f * kt - 1.0f) / (float)kt;
                    const float bn = (float)(kt - 1) / (float)kt;
                    #pragma unroll
                    for (int i = 0; i < 16; i++) {
                        float p2 = an * t[i] * pb[i] - bn * pa[i];
                        pa[i] = pb[i];
                        pb[i] = p2;
                    }
                }
                #pragma unroll
                for (int mt = 0; mt < 2; mt++) {
                    ah[mt][0] = pack_h(pb[IDX(mt,0,0)], pb[IDX(mt,0,1)]);
                    ah[mt][1] = pack_h(pb[IDX(mt,1,0)], pb[IDX(mt,1,1)]);
                    ah[mt][2] = pack_h(pb[IDX(mt,0,2)], pb[IDX(mt,0,3)]);
                    ah[mt][3] = pack_h(pb[IDX(mt,1,2)], pb[IDX(mt,1,3)]);
                }

                #pragma unroll
                for (int g = 0; g < 4; g++)
                    #pragma unroll
                    for (int mt = 0; mt < 2; mt++) {
                        mma_fp16(acc[mt][g * 2 + 0], ah[mt], b[g].x, b[g].y);
                        mma_fp16(acc[mt][g * 2 + 1], ah[mt], b[g].z, b[g].w);
                    }
            }
        }

        // epilogue
        const int g = lr;
        #pragma unroll
        for (int mt = 0; mt < 2; mt++) {
            const int mb = m0 + wm * 32 + mt * 16;
            #pragma unroll
            for (int j = 0; j < 8; j++) {
                const int f = f0 + wn * 64 + j * 8 + tig * 2;
                float2 lo = make_float2(acc[mt][j][0], acc[mt][j][1]);
                float2 hi = make_float2(acc[mt][j][2], acc[mt][j][3]);
                *(float2*)(out + (size_t)(mb + g)     * F_ + f) = lo;
                *(float2*)(out + (size_t)(mb + g + 8) * F_ + f) = hi;
            }
        }
    }
}

// ---------------- launch ---------------------------------------------------
extern "C" void kernel_launch(void* const* d_in, const int* in_sizes, int n_in,
                              void* d_out, int out_size) {
    const float* x   = (const float*)d_in[0];   // [8192,256]
    const float* cen = (const float*)d_in[1];   // [512,256]
    const float* w   = (const float*)d_in[2];   // [512,9,256]
    float* out = (float*)d_out;                 // [8192,256]

    k_prep_all<<<NB_ALL, 256>>>(x, cen, w);
    k_main<<<GRID_MAIN, 256>>>(out);
}